// round 5
// baseline (speedup 1.0000x reference)
#include <cuda_runtime.h>
#include <cuda_fp16.h>
#include <float.h>
#include <stdint.h>

// Morphological dilation2d (max-plus conv):
//   out[b,o,h,w] = max_{c,i,j}( x_pad[b,c,h+i,w+j] + wt[o,c,i,j] ),  zero padding participates.
// B=C=O=4, H=W=1024, k=5, pad=2.
//
// R5: issue-slot diet. fp16x2 packed over output channels (o0,o1)/(o2,o3);
// TPT=8 with vectorized LDS.128 smem reads; per-channel smem staging to hold
// 4 CTAs/SM at TW=64.

#define TH 32
#define TW 64
#define TPT 8               // w-outputs per thread
#define XROWS (TH + 4)      // 36
#define XCOLS (TW + 4)      // 68 (half2 cols actually used)
#define XSTRIDE 72          // half2 stride: 288B/row, 16B-aligned vector loads

__global__ __launch_bounds__(256, 4)
void Morphology_84602265797171_kernel(const float* __restrict__ x,
                                      const float* __restrict__ wt,
                                      float* __restrict__ out) {
    __shared__ half2 xs[XROWS * XSTRIDE];              // one channel staged: 10.1 KB
    __shared__ __align__(16) half2 wsm[20 * 12];       // [ci][0..3]=w01 j0..3, [4..7]=w23 j0..3, [8]=w01 j4, [9]=w23 j4

    const int tid = threadIdx.x;
    const int b  = blockIdx.z;
    const int h0 = blockIdx.y * TH;
    const int w0 = blockIdx.x * TW;

    // --- prepack weights: wt layout [o][c][i][j]; tid -> (ci=tid/5, j=tid%5) ---
    if (tid < 100) {
        int ci = tid / 5;
        int j  = tid % 5;
        half2 w01 = __floats2half2_rn(wt[tid],       wt[tid + 100]);
        half2 w23 = __floats2half2_rn(wt[tid + 200], wt[tid + 300]);
        if (j < 4) {
            wsm[ci * 12 + j]     = w01;
            wsm[ci * 12 + 4 + j] = w23;
        } else {
            wsm[ci * 12 + 8] = w01;
            wsm[ci * 12 + 9] = w23;
        }
    }

    const int th = tid >> 3;            // 0..31  output row in tile
    const int tw = (tid & 7) * TPT;     // 0..56  first output col in tile

    half2 acc01[TPT], acc23[TPT];
    const half2 NEG = __half2half2(__float2half_rn(-60000.0f));
    #pragma unroll
    for (int t = 0; t < TPT; t++) { acc01[t] = NEG; acc23[t] = NEG; }

    const float* xb = x + (size_t)b * 4 * 1024 * 1024;

    #pragma unroll 1
    for (int c = 0; c < 4; c++) {
        // ---- stage channel c tile (with halo) as duplicated half2 ----
        __syncthreads();                 // previous phase fully consumed
        const float* xc = xb + (size_t)c * 1024 * 1024;
        #pragma unroll 1
        for (int idx = tid; idx < XROWS * (XCOLS / 2); idx += 256) {
            int r   = idx / (XCOLS / 2);
            int p   = idx % (XCOLS / 2);
            int col = p * 2;
            int gh  = h0 - 2 + r;
            int gw  = w0 - 2 + col;
            float v0 = 0.0f, v1 = 0.0f;
            if ((unsigned)gh < 1024u) {
                const float* grow = xc + (size_t)gh * 1024;
                if ((unsigned)gw < 1023u) {            // fast path: both in range, 8B-aligned
                    float2 g = *(const float2*)(grow + gw);
                    v0 = g.x; v1 = g.y;
                } else {
                    if ((unsigned)gw < 1024u)       v0 = grow[gw];
                    if ((unsigned)(gw + 1) < 1024u) v1 = grow[gw + 1];
                }
            }
            half2 d0 = __half2half2(__float2half_rn(v0));
            half2 d1 = __half2half2(__float2half_rn(v1));
            half2* dst = &xs[r * XSTRIDE + col];
            dst[0] = d0; dst[1] = d1;
        }
        __syncthreads();

        // ---- accumulate over i, j for this channel ----
        #pragma unroll
        for (int i = 0; i < 5; i++) {
            const int ci = c * 5 + i;

            // 12 x pairs: three LDS.128
            half2 xv[12];
            {
                const uint4* xq = (const uint4*)&xs[(th + i) * XSTRIDE + tw];
                *(uint4*)&xv[0] = xq[0];
                *(uint4*)&xv[4] = xq[1];
                *(uint4*)&xv[8] = xq[2];
            }
            // 10 weight pairs: 2x LDS.128 + 1x LDS.64 (uniform -> broadcast)
            half2 w01[5], w23[5];
            {
                const uint4* wq = (const uint4*)&wsm[ci * 12];
                *(uint4*)&w01[0] = wq[0];
                *(uint4*)&w23[0] = wq[1];
                uint2 q2 = *(const uint2*)&wsm[ci * 12 + 8];
                w01[4] = *(half2*)&q2.x;
                w23[4] = *(half2*)&q2.y;
            }

            #pragma unroll
            for (int j = 0; j < 5; j++) {
                #pragma unroll
                for (int t = 0; t < TPT; t++) {
                    half2 xp = xv[t + j];
                    acc01[t] = __hmax2(acc01[t], __hadd2(xp, w01[j]));
                    acc23[t] = __hmax2(acc23[t], __hadd2(xp, w23[j]));
                }
            }
        }
    }

    // ---- epilogue: unpack to fp32, two float4 per output channel ----
    float a0[TPT], a1[TPT], a2[TPT], a3[TPT];
    #pragma unroll
    for (int t = 0; t < TPT; t++) {
        float2 f01 = __half22float2(acc01[t]);
        float2 f23 = __half22float2(acc23[t]);
        a0[t] = f01.x; a1[t] = f01.y; a2[t] = f23.x; a3[t] = f23.y;
    }
    const size_t plane = (size_t)1024 * 1024;
    float* ob = out + (size_t)b * 4 * plane + (size_t)(h0 + th) * 1024 + (w0 + tw);

    *(float4*)(ob + 0 * plane)     = make_float4(a0[0], a0[1], a0[2], a0[3]);
    *(float4*)(ob + 0 * plane + 4) = make_float4(a0[4], a0[5], a0[6], a0[7]);
    *(float4*)(ob + 1 * plane)     = make_float4(a1[0], a1[1], a1[2], a1[3]);
    *(float4*)(ob + 1 * plane + 4) = make_float4(a1[4], a1[5], a1[6], a1[7]);
    *(float4*)(ob + 2 * plane)     = make_float4(a2[0], a2[1], a2[2], a2[3]);
    *(float4*)(ob + 2 * plane + 4) = make_float4(a2[4], a2[5], a2[6], a2[7]);
    *(float4*)(ob + 3 * plane)     = make_float4(a3[0], a3[1], a3[2], a3[3]);
    *(float4*)(ob + 3 * plane + 4) = make_float4(a3[4], a3[5], a3[6], a3[7]);
}

extern "C" void kernel_launch(void* const* d_in, const int* in_sizes, int n_in,
                              void* d_out, int out_size) {
    const float* x  = (const float*)d_in[0];   // (4,4,1024,1024) f32
    const float* wt = (const float*)d_in[1];   // (4,4,5,5) f32
    float* out = (float*)d_out;                // (4,4,1024,1024) f32

    dim3 grid(1024 / TW, 1024 / TH, 4);        // (16, 32, 4)
    dim3 block(256);
    Morphology_84602265797171_kernel<<<grid, block>>>(x, wt, out);
}

// round 6
// speedup vs baseline: 1.0830x; 1.0830x over previous
#include <cuda_runtime.h>
#include <cuda_fp16.h>
#include <float.h>
#include <stdint.h>

// Morphological dilation2d (max-plus conv):
//   out[b,o,h,w] = max_{c,i,j}( x_pad[b,c,h+i,w+j] + wt[o,c,i,j] ),  zero padding participates.
// B=C=O=4, H=W=1024, k=5, pad=2.
//
// R6: R4 single-phase structure (all 4 channels resident, ONE sync) + R5 slot
// diet (TPT=8, LDS.128 reads, packed weights). fp16x2 over output channels.

#define TH 32
#define TW 64
#define TPT 8               // w-outputs per thread
#define XROWS (TH + 4)      // 36
#define XCOLS (TW + 4)      // 68 half2 columns
#define XSTRIDE 68          // 272B row: 16B-aligned, 272 % 128 = 16 -> <=2-way conflicts

__global__ __launch_bounds__(256, 5)
void Morphology_84602265797171_kernel(const float* __restrict__ x,
                                      const float* __restrict__ wt,
                                      float* __restrict__ out) {
    __shared__ half2 xs[4][XROWS][XSTRIDE];            // dup pairs (v,v); 39.2 KB
    __shared__ __align__(16) half2 wsm[20 * 12];       // [ci]: 0..3=w01 j0..3, 4..7=w23 j0..3, 8=w01 j4, 9=w23 j4

    const int tid = threadIdx.x;
    const int b  = blockIdx.z;
    const int h0 = blockIdx.y * TH;
    const int w0 = blockIdx.x * TW;

    // --- prepack weights: wt layout [o][c][i][j]; tid -> (ci=tid/5, j=tid%5) ---
    if (tid < 100) {
        int ci = tid / 5;
        int j  = tid % 5;
        half2 w01 = __floats2half2_rn(wt[tid],       wt[tid + 100]);
        half2 w23 = __floats2half2_rn(wt[tid + 200], wt[tid + 300]);
        if (j < 4) {
            wsm[ci * 12 + j]     = w01;
            wsm[ci * 12 + 4 + j] = w23;
        } else {
            wsm[ci * 12 + 8] = w01;
            wsm[ci * 12 + 9] = w23;
        }
    }

    // --- load x tile: all 4 channels with halo; float2 fast path; dup half2 ---
    const float* xb = x + (size_t)b * 4 * 1024 * 1024;
    #pragma unroll 1
    for (int idx = tid; idx < 4 * XROWS * (XCOLS / 2); idx += 256) {
        int c   = idx / (XROWS * (XCOLS / 2));
        int rem = idx % (XROWS * (XCOLS / 2));
        int r   = rem / (XCOLS / 2);
        int col = (rem % (XCOLS / 2)) * 2;
        int gh  = h0 - 2 + r;
        int gw  = w0 - 2 + col;
        float v0 = 0.0f, v1 = 0.0f;
        if ((unsigned)gh < 1024u) {
            const float* grow = xb + (size_t)c * 1024 * 1024 + (size_t)gh * 1024;
            if ((unsigned)gw < 1023u) {               // both in-range, 8B-aligned
                float2 g = *(const float2*)(grow + gw);
                v0 = g.x; v1 = g.y;
            } else {
                if ((unsigned)gw < 1024u)       v0 = grow[gw];
                if ((unsigned)(gw + 1) < 1024u) v1 = grow[gw + 1];
            }
        }
        xs[c][r][col]     = __half2half2(__float2half_rn(v0));
        xs[c][r][col + 1] = __half2half2(__float2half_rn(v1));
    }
    __syncthreads();

    const int th = tid >> 3;            // 0..31  output row in tile
    const int tw = (tid & 7) * TPT;     // 0..56  first output col (32B-aligned)

    half2 acc01[TPT], acc23[TPT];
    const half2 NEG = __half2half2(__float2half_rn(-60000.0f));
    #pragma unroll
    for (int t = 0; t < TPT; t++) { acc01[t] = NEG; acc23[t] = NEG; }

    #pragma unroll 1
    for (int c = 0; c < 4; c++) {
        #pragma unroll
        for (int i = 0; i < 5; i++) {
            const int ci = c * 5 + i;

            // 12 x pairs: three LDS.128
            half2 xv[12];
            {
                const uint4* xq = (const uint4*)&xs[c][th + i][tw];
                *(uint4*)&xv[0] = xq[0];
                *(uint4*)&xv[4] = xq[1];
                *(uint4*)&xv[8] = xq[2];
            }
            // 10 weight pairs: 2x LDS.128 + 1x LDS.64 (uniform -> broadcast)
            half2 w01[5], w23[5];
            {
                const uint4* wq = (const uint4*)&wsm[ci * 12];
                *(uint4*)&w01[0] = wq[0];
                *(uint4*)&w23[0] = wq[1];
                uint2 q2 = *(const uint2*)&wsm[ci * 12 + 8];
                w01[4] = *(half2*)&q2.x;
                w23[4] = *(half2*)&q2.y;
            }

            #pragma unroll
            for (int j = 0; j < 5; j++) {
                #pragma unroll
                for (int t = 0; t < TPT; t++) {
                    half2 xp = xv[t + j];
                    acc01[t] = __hmax2(acc01[t], __hadd2(xp, w01[j]));
                    acc23[t] = __hmax2(acc23[t], __hadd2(xp, w23[j]));
                }
            }
        }
    }

    // --- epilogue: unpack to fp32, two float4 per output channel ---
    float a0[TPT], a1[TPT], a2[TPT], a3[TPT];
    #pragma unroll
    for (int t = 0; t < TPT; t++) {
        float2 f01 = __half22float2(acc01[t]);
        float2 f23 = __half22float2(acc23[t]);
        a0[t] = f01.x; a1[t] = f01.y; a2[t] = f23.x; a3[t] = f23.y;
    }
    const size_t plane = (size_t)1024 * 1024;
    float* ob = out + (size_t)b * 4 * plane + (size_t)(h0 + th) * 1024 + (w0 + tw);

    *(float4*)(ob + 0 * plane)     = make_float4(a0[0], a0[1], a0[2], a0[3]);
    *(float4*)(ob + 0 * plane + 4) = make_float4(a0[4], a0[5], a0[6], a0[7]);
    *(float4*)(ob + 1 * plane)     = make_float4(a1[0], a1[1], a1[2], a1[3]);
    *(float4*)(ob + 1 * plane + 4) = make_float4(a1[4], a1[5], a1[6], a1[7]);
    *(float4*)(ob + 2 * plane)     = make_float4(a2[0], a2[1], a2[2], a2[3]);
    *(float4*)(ob + 2 * plane + 4) = make_float4(a2[4], a2[5], a2[6], a2[7]);
    *(float4*)(ob + 3 * plane)     = make_float4(a3[0], a3[1], a3[2], a3[3]);
    *(float4*)(ob + 3 * plane + 4) = make_float4(a3[4], a3[5], a3[6], a3[7]);
}

extern "C" void kernel_launch(void* const* d_in, const int* in_sizes, int n_in,
                              void* d_out, int out_size) {
    const float* x  = (const float*)d_in[0];   // (4,4,1024,1024) f32
    const float* wt = (const float*)d_in[1];   // (4,4,5,5) f32
    float* out = (float*)d_out;                // (4,4,1024,1024) f32

    dim3 grid(1024 / TW, 1024 / TH, 4);        // (16, 32, 4)
    dim3 block(256);
    Morphology_84602265797171_kernel<<<grid, block>>>(x, wt, out);
}

// round 7
// speedup vs baseline: 1.1109x; 1.0258x over previous
#include <cuda_runtime.h>
#include <cuda_fp16.h>
#include <float.h>
#include <stdint.h>

// Morphological dilation2d (max-plus conv):
//   out[b,o,h,w] = max_{c,i,j}( x_pad[b,c,h+i,w+j] + wt[o,c,i,j] ),  zero padding participates.
// B=C=O=4, H=W=1024, k=5, pad=2.
//
// R7: R6 inner loop (fp16x2 over o-pairs, LDS.128 reads) with finer CTAs:
// TH=16, 128 threads, 22.7KB smem -> 10 CTAs/SM (40 warps), 4096 blocks.

#define TH 16
#define TW 64
#define TPT 8               // w-outputs per thread
#define XROWS (TH + 4)      // 20
#define XCOLS (TW + 4)      // 68 half2 columns
#define XSTRIDE 68          // 272B row: 16B-aligned; 8-lane row groups are conflict-free

__global__ __launch_bounds__(128, 10)
void Morphology_84602265797171_kernel(const float* __restrict__ x,
                                      const float* __restrict__ wt,
                                      float* __restrict__ out) {
    __shared__ half2 xs[4][XROWS][XSTRIDE];            // dup pairs (v,v); 21.8 KB
    __shared__ __align__(16) half2 wsm[20 * 12];       // [ci]: 0..3=w01 j0..3, 4..7=w23 j0..3, 8=w01 j4, 9=w23 j4

    const int tid = threadIdx.x;
    const int b  = blockIdx.z;
    const int h0 = blockIdx.y * TH;
    const int w0 = blockIdx.x * TW;

    // --- prepack weights: wt layout [o][c][i][j]; tid -> (ci=tid/5, j=tid%5) ---
    if (tid < 100) {
        int ci = tid / 5;
        int j  = tid % 5;
        half2 w01 = __floats2half2_rn(wt[tid],       wt[tid + 100]);
        half2 w23 = __floats2half2_rn(wt[tid + 200], wt[tid + 300]);
        if (j < 4) {
            wsm[ci * 12 + j]     = w01;
            wsm[ci * 12 + 4 + j] = w23;
        } else {
            wsm[ci * 12 + 8] = w01;
            wsm[ci * 12 + 9] = w23;
        }
    }

    // --- load x tile: all 4 channels with halo; float2 fast path; dup half2 ---
    const float* xb = x + (size_t)b * 4 * 1024 * 1024;
    #pragma unroll 1
    for (int idx = tid; idx < 4 * XROWS * (XCOLS / 2); idx += 128) {
        int c   = idx / (XROWS * (XCOLS / 2));
        int rem = idx % (XROWS * (XCOLS / 2));
        int r   = rem / (XCOLS / 2);
        int col = (rem % (XCOLS / 2)) * 2;
        int gh  = h0 - 2 + r;
        int gw  = w0 - 2 + col;
        float v0 = 0.0f, v1 = 0.0f;
        if ((unsigned)gh < 1024u) {
            const float* grow = xb + (size_t)c * 1024 * 1024 + (size_t)gh * 1024;
            if ((unsigned)gw < 1023u) {               // both in-range, 8B-aligned
                float2 g = *(const float2*)(grow + gw);
                v0 = g.x; v1 = g.y;
            } else {
                if ((unsigned)gw < 1024u)       v0 = grow[gw];
                if ((unsigned)(gw + 1) < 1024u) v1 = grow[gw + 1];
            }
        }
        xs[c][r][col]     = __half2half2(__float2half_rn(v0));
        xs[c][r][col + 1] = __half2half2(__float2half_rn(v1));
    }
    __syncthreads();

    const int th = tid >> 3;            // 0..15  output row in tile
    const int tw = (tid & 7) * TPT;     // 0..56  first output col (32B-aligned)

    half2 acc01[TPT], acc23[TPT];
    const half2 NEG = __half2half2(__float2half_rn(-60000.0f));
    #pragma unroll
    for (int t = 0; t < TPT; t++) { acc01[t] = NEG; acc23[t] = NEG; }

    #pragma unroll 1
    for (int c = 0; c < 4; c++) {
        #pragma unroll
        for (int i = 0; i < 5; i++) {
            const int ci = c * 5 + i;

            // 12 x pairs: three LDS.128 (8 lanes/row -> conflict-free groups)
            half2 xv[12];
            {
                const uint4* xq = (const uint4*)&xs[c][th + i][tw];
                *(uint4*)&xv[0] = xq[0];
                *(uint4*)&xv[4] = xq[1];
                *(uint4*)&xv[8] = xq[2];
            }
            // 10 weight pairs: 2x LDS.128 + 1x LDS.64 (uniform -> broadcast)
            half2 w01[5], w23[5];
            {
                const uint4* wq = (const uint4*)&wsm[ci * 12];
                *(uint4*)&w01[0] = wq[0];
                *(uint4*)&w23[0] = wq[1];
                uint2 q2 = *(const uint2*)&wsm[ci * 12 + 8];
                w01[4] = *(half2*)&q2.x;
                w23[4] = *(half2*)&q2.y;
            }

            #pragma unroll
            for (int j = 0; j < 5; j++) {
                #pragma unroll
                for (int t = 0; t < TPT; t++) {
                    half2 xp = xv[t + j];
                    acc01[t] = __hmax2(acc01[t], __hadd2(xp, w01[j]));
                    acc23[t] = __hmax2(acc23[t], __hadd2(xp, w23[j]));
                }
            }
        }
    }

    // --- epilogue: unpack to fp32, two float4 per output channel ---
    float a0[TPT], a1[TPT], a2[TPT], a3[TPT];
    #pragma unroll
    for (int t = 0; t < TPT; t++) {
        float2 f01 = __half22float2(acc01[t]);
        float2 f23 = __half22float2(acc23[t]);
        a0[t] = f01.x; a1[t] = f01.y; a2[t] = f23.x; a3[t] = f23.y;
    }
    const size_t plane = (size_t)1024 * 1024;
    float* ob = out + (size_t)b * 4 * plane + (size_t)(h0 + th) * 1024 + (w0 + tw);

    *(float4*)(ob + 0 * plane)     = make_float4(a0[0], a0[1], a0[2], a0[3]);
    *(float4*)(ob + 0 * plane + 4) = make_float4(a0[4], a0[5], a0[6], a0[7]);
    *(float4*)(ob + 1 * plane)     = make_float4(a1[0], a1[1], a1[2], a1[3]);
    *(float4*)(ob + 1 * plane + 4) = make_float4(a1[4], a1[5], a1[6], a1[7]);
    *(float4*)(ob + 2 * plane)     = make_float4(a2[0], a2[1], a2[2], a2[3]);
    *(float4*)(ob + 2 * plane + 4) = make_float4(a2[4], a2[5], a2[6], a2[7]);
    *(float4*)(ob + 3 * plane)     = make_float4(a3[0], a3[1], a3[2], a3[3]);
    *(float4*)(ob + 3 * plane + 4) = make_float4(a3[4], a3[5], a3[6], a3[7]);
}

extern "C" void kernel_launch(void* const* d_in, const int* in_sizes, int n_in,
                              void* d_out, int out_size) {
    const float* x  = (const float*)d_in[0];   // (4,4,1024,1024) f32
    const float* wt = (const float*)d_in[1];   // (4,4,5,5) f32
    float* out = (float*)d_out;                // (4,4,1024,1024) f32

    dim3 grid(1024 / TW, 1024 / TH, 4);        // (16, 64, 4)
    dim3 block(128);
    Morphology_84602265797171_kernel<<<grid, block>>>(x, wt, out);
}

// round 8
// speedup vs baseline: 1.1370x; 1.0235x over previous
#include <cuda_runtime.h>
#include <cuda_fp16.h>
#include <float.h>
#include <stdint.h>

// Morphological dilation2d (max-plus conv):
//   out[b,o,h,w] = max_{c,i,j}( x_pad[b,c,h+i,w+j] + wt[o,c,i,j] ),  zero padding participates.
// B=C=O=4, H=W=1024, k=5, pad=2.
//
// R8: R4's conflict-free lane geometry (tw = lane*16B -> every LDS.128
// quarter-warp is 128B contiguous, zero bank conflicts) + R6's slot economy
// (vector loads, packed weights). fp16x2 over output-channel pairs.

#define TH 32
#define TW 32
#define TPT 4               // w-outputs per thread
#define XROWS (TH + 4)      // 36
#define XCOLS (TW + 4)      // 36 half2 columns
#define XSTRIDE 36          // 144B row stride: 16B-aligned, quarters are per-row

__global__ __launch_bounds__(256, 5)
void Morphology_84602265797171_kernel(const float* __restrict__ x,
                                      const float* __restrict__ wt,
                                      float* __restrict__ out) {
    __shared__ __align__(16) half2 xs[4][XROWS][XSTRIDE];   // dup pairs (v,v); 20.7 KB
    __shared__ __align__(16) half2 wsm[20 * 12];  // [ci]: 0..3=w01 j0..3, 4..7=w23 j0..3, 8=w01 j4, 9=w23 j4

    const int tid = threadIdx.x;
    const int b  = blockIdx.z;
    const int h0 = blockIdx.y * TH;
    const int w0 = blockIdx.x * TW;

    // --- prepack weights: wt layout [o][c][i][j]; tid -> (ci=tid/5, j=tid%5) ---
    if (tid < 100) {
        int ci = tid / 5;
        int j  = tid % 5;
        half2 w01 = __floats2half2_rn(wt[tid],       wt[tid + 100]);
        half2 w23 = __floats2half2_rn(wt[tid + 200], wt[tid + 300]);
        if (j < 4) {
            wsm[ci * 12 + j]     = w01;
            wsm[ci * 12 + 4 + j] = w23;
        } else {
            wsm[ci * 12 + 8] = w01;
            wsm[ci * 12 + 9] = w23;
        }
    }

    // --- load x tile: all 4 channels with halo; float2 fast path; dup half2 ---
    const float* xb = x + (size_t)b * 4 * 1024 * 1024;
    #pragma unroll 1
    for (int idx = tid; idx < 4 * XROWS * (XCOLS / 2); idx += 256) {
        int c   = idx / (XROWS * (XCOLS / 2));
        int rem = idx % (XROWS * (XCOLS / 2));
        int r   = rem / (XCOLS / 2);
        int col = (rem % (XCOLS / 2)) * 2;
        int gh  = h0 - 2 + r;
        int gw  = w0 - 2 + col;
        float v0 = 0.0f, v1 = 0.0f;
        if ((unsigned)gh < 1024u) {
            const float* grow = xb + (size_t)c * 1024 * 1024 + (size_t)gh * 1024;
            if ((unsigned)gw < 1023u) {               // both in-range, 8B-aligned
                float2 g = *(const float2*)(grow + gw);
                v0 = g.x; v1 = g.y;
            } else {
                if ((unsigned)gw < 1024u)       v0 = grow[gw];
                if ((unsigned)(gw + 1) < 1024u) v1 = grow[gw + 1];
            }
        }
        xs[c][r][col]     = __half2half2(__float2half_rn(v0));
        xs[c][r][col + 1] = __half2half2(__float2half_rn(v1));
    }
    __syncthreads();

    const int th = tid >> 3;            // 0..31  output row in tile (lanes 0-7 share a row)
    const int tw = (tid & 7) * TPT;     // 0..28  first output col; 16B per lane -> conflict-free

    half2 acc01[TPT], acc23[TPT];
    const half2 NEG = __half2half2(__float2half_rn(-60000.0f));
    #pragma unroll
    for (int t = 0; t < TPT; t++) { acc01[t] = NEG; acc23[t] = NEG; }

    #pragma unroll 1
    for (int c = 0; c < 4; c++) {
        #pragma unroll
        for (int i = 0; i < 5; i++) {
            const int ci = c * 5 + i;

            // 8 x pairs: two LDS.128, each quarter-warp reads 128B contiguous
            half2 xv[8];
            {
                const uint4* xq = (const uint4*)&xs[c][th + i][tw];
                *(uint4*)&xv[0] = xq[0];
                *(uint4*)&xv[4] = xq[1];
            }
            // 10 weight pairs: 2x LDS.128 + 1x LDS.64 (uniform -> broadcast)
            half2 w01[5], w23[5];
            {
                const uint4* wq = (const uint4*)&wsm[ci * 12];
                *(uint4*)&w01[0] = wq[0];
                *(uint4*)&w23[0] = wq[1];
                uint2 q2 = *(const uint2*)&wsm[ci * 12 + 8];
                w01[4] = *(half2*)&q2.x;
                w23[4] = *(half2*)&q2.y;
            }

            #pragma unroll
            for (int j = 0; j < 5; j++) {
                #pragma unroll
                for (int t = 0; t < TPT; t++) {
                    half2 xp = xv[t + j];
                    acc01[t] = __hmax2(acc01[t], __hadd2(xp, w01[j]));
                    acc23[t] = __hmax2(acc23[t], __hadd2(xp, w23[j]));
                }
            }
        }
    }

    // --- epilogue: unpack to fp32, one float4 per output channel ---
    float a0[TPT], a1[TPT], a2[TPT], a3[TPT];
    #pragma unroll
    for (int t = 0; t < TPT; t++) {
        float2 f01 = __half22float2(acc01[t]);
        float2 f23 = __half22float2(acc23[t]);
        a0[t] = f01.x; a1[t] = f01.y; a2[t] = f23.x; a3[t] = f23.y;
    }
    const size_t plane = (size_t)1024 * 1024;
    float* ob = out + (size_t)b * 4 * plane + (size_t)(h0 + th) * 1024 + (w0 + tw);

    *(float4*)(ob + 0 * plane) = make_float4(a0[0], a0[1], a0[2], a0[3]);
    *(float4*)(ob + 1 * plane) = make_float4(a1[0], a1[1], a1[2], a1[3]);
    *(float4*)(ob + 2 * plane) = make_float4(a2[0], a2[1], a2[2], a2[3]);
    *(float4*)(ob + 3 * plane) = make_float4(a3[0], a3[1], a3[2], a3[3]);
}

extern "C" void kernel_launch(void* const* d_in, const int* in_sizes, int n_in,
                              void* d_out, int out_size) {
    const float* x  = (const float*)d_in[0];   // (4,4,1024,1024) f32
    const float* wt = (const float*)d_in[1];   // (4,4,5,5) f32
    float* out = (float*)d_out;                // (4,4,1024,1024) f32

    dim3 grid(1024 / TW, 1024 / TH, 4);        // (32, 32, 4)
    dim3 block(256);
    Morphology_84602265797171_kernel<<<grid, block>>>(x, wt, out);
}

// round 10
// speedup vs baseline: 1.3276x; 1.1676x over previous
#include <cuda_runtime.h>
#include <cuda_fp16.h>
#include <float.h>
#include <stdint.h>

// Morphological dilation2d (max-plus conv):
//   out[b,o,h,w] = max_{c,i,j}( x_pad[b,c,h+i,w+j] + wt[o,c,i,j] ),  zero padding participates.
// B=C=O=4, H=W=1024, k=5, pad=2.
//
// R10: R9 design with the nvcc ICE fixed (no compound literals).
// Dual column-group TPT=8, branchless interior prologue, fp16x2 over o-pairs,
// conflict-free 16B-lane LDS.128 geometry. 128 thr, 10 CTAs/SM.

#define TH 16
#define TW 64
#define GP 4                 // outputs per group per thread
#define XROWS (TH + 4)       // 20
#define XCOLS 68             // half2 columns used (64 + halo 4)
#define XSTRIDE 72           // half2 stride: 288B, 16B-aligned

// duplicate low/high half of a packed half2 pair: returns raw b32
__device__ __forceinline__ unsigned dup_lo_u(unsigned p) {
    unsigned r; asm("prmt.b32 %0, %1, %1, 0x1010;" : "=r"(r) : "r"(p));
    return r;
}
__device__ __forceinline__ unsigned dup_hi_u(unsigned p) {
    unsigned r; asm("prmt.b32 %0, %1, %1, 0x3232;" : "=r"(r) : "r"(p));
    return r;
}

__global__ __launch_bounds__(128, 10)
void Morphology_84602265797171_kernel(const float* __restrict__ x,
                                      const float* __restrict__ wt,
                                      float* __restrict__ out) {
    __shared__ __align__(16) half2 xs[4][XROWS][XSTRIDE];   // dup pairs (v,v); 23.0 KB
    __shared__ __align__(16) uint4 wsm4[20][3];  // [ci]: 0=w01 j0-3, 1=w23 j0-3, 2={w01j4,w23j4,-,-}

    const int tid = threadIdx.x;
    const int b  = blockIdx.z;
    const int h0 = blockIdx.y * TH;
    const int w0 = blockIdx.x * TW;

    // --- prepack weights: wt layout [o][c][i][j]; tid -> (ci=tid/5, j=tid%5) ---
    if (tid < 100) {
        int ci = tid / 5;
        int j  = tid % 5;
        half2 w01 = __floats2half2_rn(wt[tid],       wt[tid + 100]);
        half2 w23 = __floats2half2_rn(wt[tid + 200], wt[tid + 300]);
        half2* base = (half2*)&wsm4[ci][0];
        if (j < 4) {
            base[j]     = w01;   // words 0..3 of uint4[0]
            base[4 + j] = w23;   // words 0..3 of uint4[1]
        } else {
            base[8] = w01;       // uint4[2].x
            base[9] = w23;       // uint4[2].y
        }
    }

    // --- stage x tile: 4 channels, 20 rows, 68 half2 cols (dup pairs) ---
    const float* xb = x + (size_t)b * 4 * 1024 * 1024;
    const bool interior = (h0 >= 2) && (h0 + TH + 2 <= 1024) &&
                          (w0 >= 2) && (w0 + XCOLS - 2 <= 1024);
    if (interior) {
        // branchless: 4 elements per step via 2x LDG.64 (8B-aligned), STS.128
        #pragma unroll 1
        for (int g = tid; g < 4 * XROWS * (XCOLS / 4); g += 128) {
            int c   = g / (XROWS * (XCOLS / 4));
            int rem = g % (XROWS * (XCOLS / 4));
            int r   = rem / (XCOLS / 4);
            int q   = rem % (XCOLS / 4);
            const float* grow = xb + (size_t)c * 1024 * 1024 + (size_t)(h0 - 2 + r) * 1024 + (w0 - 2);
            float2 g0 = *(const float2*)(grow + q * 4);
            float2 g1 = *(const float2*)(grow + q * 4 + 2);
            half2 p0 = __floats2half2_rn(g0.x, g0.y);
            half2 p1 = __floats2half2_rn(g1.x, g1.y);
            unsigned u0 = *(unsigned*)&p0;
            unsigned u1 = *(unsigned*)&p1;
            uint4 v4 = make_uint4(dup_lo_u(u0), dup_hi_u(u0),
                                  dup_lo_u(u1), dup_hi_u(u1));
            *(uint4*)&xs[c][r][q * 4] = v4;
        }
    } else {
        // border: predicated scalar loads
        #pragma unroll 1
        for (int g = tid; g < 4 * XROWS * (XCOLS / 4); g += 128) {
            int c   = g / (XROWS * (XCOLS / 4));
            int rem = g % (XROWS * (XCOLS / 4));
            int r   = rem / (XCOLS / 4);
            int q   = rem % (XCOLS / 4);
            int gh  = h0 - 2 + r;
            const float* grow = xb + (size_t)c * 1024 * 1024 + (size_t)gh * 1024;
            float v[4];
            #pragma unroll
            for (int e = 0; e < 4; e++) {
                int gw = w0 - 2 + q * 4 + e;
                bool ok = ((unsigned)gh < 1024u) & ((unsigned)gw < 1024u);
                v[e] = ok ? grow[gw] : 0.0f;
            }
            half2* dst = &xs[c][r][q * 4];
            dst[0] = __half2half2(__float2half_rn(v[0]));
            dst[1] = __half2half2(__float2half_rn(v[1]));
            dst[2] = __half2half2(__float2half_rn(v[2]));
            dst[3] = __half2half2(__float2half_rn(v[3]));
        }
    }
    __syncthreads();

    const int th  = tid >> 3;            // 0..15   output row in tile
    const int tw0 = (tid & 7) * GP;      // 0..28   group0 first col (16B per lane)

    half2 a01[2][GP], a23[2][GP];        // [group][t]
    const half2 NEG = __half2half2(__float2half_rn(-60000.0f));
    #pragma unroll
    for (int ggg = 0; ggg < 2; ggg++)
        #pragma unroll
        for (int t = 0; t < GP; t++) { a01[ggg][t] = NEG; a23[ggg][t] = NEG; }

    #pragma unroll 1
    for (int c = 0; c < 4; c++) {
        #pragma unroll
        for (int i = 0; i < 5; i++) {
            const int ci = c * 5 + i;

            // weights: 3 uniform LDS.128 (broadcast)
            half2 w01[5], w23[5];
            {
                uint4 q0 = wsm4[ci][0];
                uint4 q1 = wsm4[ci][1];
                uint4 q2 = wsm4[ci][2];
                *(uint4*)&w01[0] = q0;
                *(uint4*)&w23[0] = q1;
                w01[4] = *(half2*)&q2.x;
                w23[4] = *(half2*)&q2.y;
            }
            const half2* rowp = &xs[c][th + i][0];

            #pragma unroll
            for (int grp = 0; grp < 2; grp++) {
                const int twg = tw0 + grp * 32;
                // 8 x pairs: 2x LDS.128, each quarter-warp contiguous 128B
                half2 xv[8];
                {
                    const uint4* xq = (const uint4*)(rowp + twg);
                    *(uint4*)&xv[0] = xq[0];
                    *(uint4*)&xv[4] = xq[1];
                }
                #pragma unroll
                for (int j = 0; j < 5; j++) {
                    #pragma unroll
                    for (int t = 0; t < GP; t++) {
                        half2 xp = xv[t + j];
                        a01[grp][t] = __hmax2(a01[grp][t], __hadd2(xp, w01[j]));
                        a23[grp][t] = __hmax2(a23[grp][t], __hadd2(xp, w23[j]));
                    }
                }
            }
        }
    }

    // --- epilogue: unpack, one float4 per (o, group) ---
    const size_t plane = (size_t)1024 * 1024;
    float* ob = out + (size_t)b * 4 * plane + (size_t)(h0 + th) * 1024 + w0;

    #pragma unroll
    for (int grp = 0; grp < 2; grp++) {
        const int twg = tw0 + grp * 32;
        float f0[GP], f1[GP], f2[GP], f3[GP];
        #pragma unroll
        for (int t = 0; t < GP; t++) {
            float2 p01 = __half22float2(a01[grp][t]);
            float2 p23 = __half22float2(a23[grp][t]);
            f0[t] = p01.x; f1[t] = p01.y; f2[t] = p23.x; f3[t] = p23.y;
        }
        *(float4*)(ob + 0 * plane + twg) = make_float4(f0[0], f0[1], f0[2], f0[3]);
        *(float4*)(ob + 1 * plane + twg) = make_float4(f1[0], f1[1], f1[2], f1[3]);
        *(float4*)(ob + 2 * plane + twg) = make_float4(f2[0], f2[1], f2[2], f2[3]);
        *(float4*)(ob + 3 * plane + twg) = make_float4(f3[0], f3[1], f3[2], f3[3]);
    }
}

extern "C" void kernel_launch(void* const* d_in, const int* in_sizes, int n_in,
                              void* d_out, int out_size) {
    const float* x  = (const float*)d_in[0];   // (4,4,1024,1024) f32
    const float* wt = (const float*)d_in[1];   // (4,4,5,5) f32
    float* out = (float*)d_out;                // (4,4,1024,1024) f32

    dim3 grid(1024 / TW, 1024 / TH, 4);        // (16, 64, 4)
    dim3 block(128);
    Morphology_84602265797171_kernel<<<grid, block>>>(x, wt, out);
}